// round 4
// baseline (speedup 1.0000x reference)
#include <cuda_runtime.h>
#include <cstdint>

// CutStripes: out[b,c,t,f] = mask(b,t) ? x[perm[b],c,t,f] : x[b,c,t,f]
// x (128,1,2048,128) f32; perm (128) i32; bgn,distance (128,4) i32.
//
// HBM-streaming kernel, MLP=8 per thread: each thread owns 8 float4 at
// stride THREADS within a 2048-float4 block slab. All 8 address
// computations happen first, then 8 front-batched 128-bit loads, then
// 8 stores. Slab is fully inside one batch b -> params block-uniform.

static constexpr int T  = 2048;
static constexpr long TOTAL4 = 128L * 2048L * 32L;   // 8,388,608 float4
static constexpr int ITEMS = 8;
static constexpr int THREADS = 256;
static constexpr int SLAB = THREADS * ITEMS;         // 2048 float4 per block

__global__ void __launch_bounds__(THREADS)
cutstripes_kernel(const float4* __restrict__ x,
                  const int*    __restrict__ perm,
                  const int*    __restrict__ bgn,
                  const int*    __restrict__ dist,
                  float4*       __restrict__ out)
{
    const unsigned base = blockIdx.x * SLAB + threadIdx.x;
    const int b = blockIdx.x >> 5;                 // (blk*2048) >> 16

    // Block-uniform stripe params + permuted batch (L1-resident).
    const int4 bg = __ldg((const int4*)(bgn  + (b << 2)));
    const int4 ds = __ldg((const int4*)(dist + (b << 2)));
    const int  pb = __ldg(perm + b);

    unsigned idx[ITEMS];
    unsigned src[ITEMS];
#pragma unroll
    for (int k = 0; k < ITEMS; k++) {
        idx[k] = base + k * THREADS;
        const int t = (idx[k] >> 5) & (T - 1);
        const bool m = ((unsigned)(t - bg.x) < (unsigned)ds.x) |
                       ((unsigned)(t - bg.y) < (unsigned)ds.y) |
                       ((unsigned)(t - bg.z) < (unsigned)ds.z) |
                       ((unsigned)(t - bg.w) < (unsigned)ds.w);
        const int src_b = m ? pb : b;
        src[k] = ((unsigned)src_b << 16) | (idx[k] & 0xFFFFu);
    }

    // Front-batched loads: 8 outstanding 128B LDGs per thread.
    float4 v[ITEMS];
#pragma unroll
    for (int k = 0; k < ITEMS; k++)
        v[k] = __ldcs(x + src[k]);          // streaming: no reuse

#pragma unroll
    for (int k = 0; k < ITEMS; k++)
        __stcs(out + idx[k], v[k]);         // streaming store
}

extern "C" void kernel_launch(void* const* d_in, const int* in_sizes, int n_in,
                              void* d_out, int out_size)
{
    const float4* x    = (const float4*)d_in[0];
    const int*    perm = (const int*)   d_in[1];
    const int*    bgn  = (const int*)   d_in[2];
    const int*    dist = (const int*)   d_in[3];
    float4*       out  = (float4*)      d_out;

    const int blocks = (int)(TOTAL4 / SLAB);   // 4096
    cutstripes_kernel<<<blocks, THREADS>>>(x, perm, bgn, dist, out);
}

// round 5
// speedup vs baseline: 1.0057x; 1.0057x over previous
#include <cuda_runtime.h>
#include <cstdint>

// CutStripes: out[b,c,t,f] = mask(b,t) ? x[perm[b],c,t,f] : x[b,c,t,f]
// x (128,1,2048,128) f32; perm (128) i32; bgn,distance (128,4) i32.
//
// HBM-streaming kernel. MLP=8 per thread with SMALL blocks (128 thr) and
// min-blocks hint so the register budget still allows ~10 CTAs/SM: both
// high occupancy AND deep front-batched loads. Slab = 1024 float4 per
// block, fully inside one batch b -> stripe params block-uniform.

static constexpr int T  = 2048;
static constexpr long TOTAL4 = 128L * 2048L * 32L;   // 8,388,608 float4
static constexpr int ITEMS = 8;
static constexpr int THREADS = 128;
static constexpr int SLAB = THREADS * ITEMS;         // 1024 float4 per block

__global__ void __launch_bounds__(THREADS, 10)
cutstripes_kernel(const float4* __restrict__ x,
                  const int*    __restrict__ perm,
                  const int*    __restrict__ bgn,
                  const int*    __restrict__ dist,
                  float4*       __restrict__ out)
{
    const unsigned base = blockIdx.x * SLAB + threadIdx.x;
    const int b = blockIdx.x >> 6;                 // (blk*1024) >> 16

    // Block-uniform stripe params + permuted batch (L1-resident).
    const int4 bg = __ldg((const int4*)(bgn  + (b << 2)));
    const int4 ds = __ldg((const int4*)(dist + (b << 2)));
    const int  pb = __ldg(perm + b);

    unsigned idx[ITEMS];
    unsigned src[ITEMS];
#pragma unroll
    for (int k = 0; k < ITEMS; k++) {
        idx[k] = base + k * THREADS;
        const int t = (idx[k] >> 5) & (T - 1);
        const bool m = ((unsigned)(t - bg.x) < (unsigned)ds.x) |
                       ((unsigned)(t - bg.y) < (unsigned)ds.y) |
                       ((unsigned)(t - bg.z) < (unsigned)ds.z) |
                       ((unsigned)(t - bg.w) < (unsigned)ds.w);
        const int src_b = m ? pb : b;
        src[k] = ((unsigned)src_b << 16) | (idx[k] & 0xFFFFu);
    }

    // Front-batched loads: up to 8 outstanding 128B LDGs per thread.
    float4 v[ITEMS];
#pragma unroll
    for (int k = 0; k < ITEMS; k++)
        v[k] = __ldcs(x + src[k]);          // streaming: no reuse

#pragma unroll
    for (int k = 0; k < ITEMS; k++)
        __stcs(out + idx[k], v[k]);         // streaming store
}

extern "C" void kernel_launch(void* const* d_in, const int* in_sizes, int n_in,
                              void* d_out, int out_size)
{
    const float4* x    = (const float4*)d_in[0];
    const int*    perm = (const int*)   d_in[1];
    const int*    bgn  = (const int*)   d_in[2];
    const int*    dist = (const int*)   d_in[3];
    float4*       out  = (float4*)      d_out;

    const int blocks = (int)(TOTAL4 / SLAB);   // 8192
    cutstripes_kernel<<<blocks, THREADS>>>(x, perm, bgn, dist, out);
}